// round 8
// baseline (speedup 1.0000x reference)
#include <cuda_runtime.h>
#include <cuda_bf16.h>

// Problem constants (B=2, H=8, S=256, D=64)
#define BATCH 2
#define NHEAD 8
#define SEQ   256
#define DIM   64
#define NROWS (BATCH * NHEAD * SEQ)   // 4096

// Persistent fused structure-attention kernel.
// grid = 148*8 CTAs, 128 threads (4 warps), 8 CTAs/SM, 64 regs/thread.
// Each CTA grid-strides over query rows (3-4 rows each): no wave
// quantization tail, no wave-transition cost.
//
// Per row:
//   Pass 1: scores[k] = q . (key[k] + key_structure[q,k])   (16-lane dot)
//   softmax (additive q-mask, /sqrt(D)); attn written out.
//   Pass 2: out[d] = sum_k attn[k] * (val[k,d] + val_structure[q,k,d])
__global__ __launch_bounds__(128, 8) void attn_struct_kernel(
    const float* __restrict__ q_,     // [B,H,S,D]
    const float* __restrict__ k_,     // [B,H,S,D]
    const float* __restrict__ v_,     // [B,H,S,D]
    const float* __restrict__ ks_,    // [B,H,S,S,D]
    const float* __restrict__ vs_,    // [B,H,S,S,D]
    const float* __restrict__ mask_,  // [B,S]
    float* __restrict__ out_,         // [B,H,S,D]
    float* __restrict__ attn_)        // [B,H,S,S]
{
    const int tid  = threadIdx.x;        // 0..127
    const int lane = tid & 31;
    const int warp = tid >> 5;           // 0..3
    const int sub  = lane & 15;          // d/4 slot
    const int half = lane >> 4;          // which of 2 k-rows

    __shared__ float sh_scores[SEQ];
    __shared__ float sh_red[4][DIM];
    __shared__ float sh_tmp[4];
    __shared__ float sh_q[DIM];

    for (int row = blockIdx.x; row < NROWS; row += gridDim.x) {
        const int qidx = row & (SEQ - 1);
        const int bh   = row >> 8;           // b*H + h
        const int b    = bh / NHEAD;

        // ---- load q row (64 floats) ----
        if (tid < DIM) sh_q[tid] = q_[(size_t)row * DIM + tid];
        __syncthreads();
        const float4 qv = *(const float4*)(sh_q + sub * 4);

        // ---- Pass 1: scores[k] = q . (key[k] + key_structure[q,k]) ----
        {
            const float* ksrow = ks_ + ((size_t)row * SEQ) * DIM
                                     + ((size_t)(warp * 64 + half)) * DIM + sub * 4;
            const float* krow  = k_  + ((size_t)bh  * SEQ) * DIM
                                     + ((size_t)(warp * 64 + half)) * DIM + sub * 4;
            #pragma unroll 4
            for (int i = 0; i < 32; ++i) {
                const int k = warp * 64 + i * 2 + half;
                float4 a = __ldcs((const float4*)(ksrow + (size_t)i * 2 * DIM));
                float4 c = *(const float4*)(krow + (size_t)i * 2 * DIM);
                float s = (a.x + c.x) * qv.x + (a.y + c.y) * qv.y
                        + (a.z + c.z) * qv.z + (a.w + c.w) * qv.w;
                #pragma unroll
                for (int off = 8; off >= 1; off >>= 1)
                    s += __shfl_xor_sync(0xffffffffu, s, off);
                if (sub == 0) sh_scores[k] = s;
            }
        }
        __syncthreads();

        // ---- softmax over 256 scores, 128 threads (2 scores/thread) ----
        const float mval = (1.0f - mask_[b * SEQ + qidx]) * -100000.0f;
        float sc0 = (sh_scores[tid]       + mval) * 0.125f;   // 1/sqrt(64)
        float sc1 = (sh_scores[tid + 128] + mval) * 0.125f;

        float m = fmaxf(sc0, sc1);
        #pragma unroll
        for (int off = 16; off >= 1; off >>= 1)
            m = fmaxf(m, __shfl_xor_sync(0xffffffffu, m, off));
        if (lane == 0) sh_tmp[warp] = m;
        __syncthreads();
        if (warp == 0) {
            float mm = sh_tmp[lane & 3];
            #pragma unroll
            for (int off = 2; off >= 1; off >>= 1)
                mm = fmaxf(mm, __shfl_xor_sync(0xffffffffu, mm, off));
            if (lane == 0) sh_tmp[0] = mm;
        }
        __syncthreads();
        const float rowmax = sh_tmp[0];

        float e0 = __expf(sc0 - rowmax);
        float e1 = __expf(sc1 - rowmax);
        float s = e0 + e1;
        #pragma unroll
        for (int off = 16; off >= 1; off >>= 1)
            s += __shfl_xor_sync(0xffffffffu, s, off);
        __syncthreads();
        if (lane == 0) sh_tmp[warp] = s;
        __syncthreads();
        if (warp == 0) {
            float ss = sh_tmp[lane & 3];
            #pragma unroll
            for (int off = 2; off >= 1; off >>= 1)
                ss += __shfl_xor_sync(0xffffffffu, ss, off);
            if (lane == 0) sh_tmp[0] = ss;
        }
        __syncthreads();
        const float inv_sum = 1.0f / sh_tmp[0];

        const float a0 = e0 * inv_sum;
        const float a1 = e1 * inv_sum;
        sh_scores[tid]       = a0;
        sh_scores[tid + 128] = a1;
        attn_[(size_t)row * SEQ + tid]       = a0;   // coalesced attn output
        attn_[(size_t)row * SEQ + tid + 128] = a1;
        __syncthreads();

        // ---- Pass 2: out[d] = sum_k attn[k]*(val[k,d]+val_structure[q,k,d]) ----
        {
            const float* vbase  = v_  + ((size_t)bh  * SEQ) * DIM
                                      + ((size_t)(warp * 64 + half)) * DIM + sub * 4;
            const float* vsbase = vs_ + ((size_t)row * SEQ) * DIM
                                      + ((size_t)(warp * 64 + half)) * DIM + sub * 4;
            float4 acc = make_float4(0.0f, 0.0f, 0.0f, 0.0f);
            #pragma unroll 4
            for (int i = 0; i < 32; ++i) {
                const int k = warp * 64 + i * 2 + half;
                const float a = sh_scores[k];
                float4 vv = *(const float4*)(vbase + (size_t)i * 2 * DIM);
                float4 sv = __ldcs((const float4*)(vsbase + (size_t)i * 2 * DIM));
                acc.x = fmaf(a, vv.x + sv.x, acc.x);
                acc.y = fmaf(a, vv.y + sv.y, acc.y);
                acc.z = fmaf(a, vv.z + sv.z, acc.z);
                acc.w = fmaf(a, vv.w + sv.w, acc.w);
            }
            // fold the two k-halves (lanes sub and sub+16 share d-range)
            acc.x += __shfl_xor_sync(0xffffffffu, acc.x, 16);
            acc.y += __shfl_xor_sync(0xffffffffu, acc.y, 16);
            acc.z += __shfl_xor_sync(0xffffffffu, acc.z, 16);
            acc.w += __shfl_xor_sync(0xffffffffu, acc.w, 16);
            if (half == 0)
                *(float4*)(&sh_red[warp][sub * 4]) = acc;
        }
        __syncthreads();

        if (tid < DIM) {
            float r = sh_red[0][tid] + sh_red[1][tid]
                    + sh_red[2][tid] + sh_red[3][tid];
            out_[(size_t)row * DIM + tid] = r;
        }
        __syncthreads();   // sh_red/sh_q/sh_scores reuse fence for next row
    }
}

extern "C" void kernel_launch(void* const* d_in, const int* in_sizes, int n_in,
                              void* d_out, int out_size) {
    const float* q    = (const float*)d_in[0];
    const float* k    = (const float*)d_in[1];
    const float* v    = (const float*)d_in[2];
    const float* ks   = (const float*)d_in[3];
    const float* vs   = (const float*)d_in[4];
    const float* mask = (const float*)d_in[5];

    float* out  = (float*)d_out;                              // [B,H,S,D]
    float* attn = out + (size_t)BATCH * NHEAD * SEQ * DIM;    // [B,H,S,S]

    const int nblocks = 148 * 8;   // persistent: one full residency wave
    attn_struct_kernel<<<nblocks, 128>>>(q, k, v, ks, vs, mask, out, attn);
}

// round 9
// speedup vs baseline: 1.0782x; 1.0782x over previous
#include <cuda_runtime.h>
#include <cuda_bf16.h>

// Problem constants (B=2, H=8, S=256, D=64)
#define BATCH 2
#define NHEAD 8
#define SEQ   256
#define DIM   64

// Fused structure-attention kernel. 128 threads/block (4 warps), 8 CTAs/SM,
// 64 regs/thread. grid = B*H*S (one CTA per query row) — R4 winner config,
// with a shortened softmax critical path between the two DRAM streams:
//   - single-barrier block reductions (all threads fold warp partials)
//   - pass 2 accumulates with unnormalized e[k]; inv_sum applied at the end
//
// Warp lane split: sub = lane&15 owns d-range [4*sub, 4*sub+4),
//                  half = lane>>4 selects one of 2 k-rows per iteration.
// Each warp owns 64 k-rows: k in [warp*64, warp*64+64).
__global__ __launch_bounds__(128, 8) void attn_struct_kernel(
    const float* __restrict__ q_,     // [B,H,S,D]
    const float* __restrict__ k_,     // [B,H,S,D]
    const float* __restrict__ v_,     // [B,H,S,D]
    const float* __restrict__ ks_,    // [B,H,S,S,D]
    const float* __restrict__ vs_,    // [B,H,S,S,D]
    const float* __restrict__ mask_,  // [B,S]
    float* __restrict__ out_,         // [B,H,S,D]
    float* __restrict__ attn_)        // [B,H,S,S]
{
    const int row  = blockIdx.x;         // (b*H + h)*S + q
    const int qidx = row & (SEQ - 1);
    const int bh   = row >> 8;           // b*H + h
    const int b    = bh / NHEAD;

    const int tid  = threadIdx.x;        // 0..127
    const int lane = tid & 31;
    const int warp = tid >> 5;           // 0..3
    const int sub  = lane & 15;          // d/4 slot
    const int half = lane >> 4;          // which of 2 k-rows

    __shared__ float sh_scores[SEQ];     // raw scores, then e[k]
    __shared__ float sh_red[4][DIM];
    __shared__ float sh_max[4];
    __shared__ float sh_sum[4];
    __shared__ float sh_q[DIM];

    // ---- load q row (64 floats) ----
    if (tid < DIM) sh_q[tid] = q_[(size_t)row * DIM + tid];
    __syncthreads();
    const float4 qv = *(const float4*)(sh_q + sub * 4);

    // ---- Pass 1: scores[k] = q . (key[k] + key_structure[q,k]) ----
    {
        const float* ksrow = ks_ + ((size_t)row * SEQ) * DIM
                                 + ((size_t)(warp * 64 + half)) * DIM + sub * 4;
        const float* krow  = k_  + ((size_t)bh  * SEQ) * DIM
                                 + ((size_t)(warp * 64 + half)) * DIM + sub * 4;
        #pragma unroll 4
        for (int i = 0; i < 32; ++i) {
            const int k = warp * 64 + i * 2 + half;
            float4 a = __ldcs((const float4*)(ksrow + (size_t)i * 2 * DIM));
            float4 c = *(const float4*)(krow + (size_t)i * 2 * DIM);
            float s = (a.x + c.x) * qv.x + (a.y + c.y) * qv.y
                    + (a.z + c.z) * qv.z + (a.w + c.w) * qv.w;
            #pragma unroll
            for (int off = 8; off >= 1; off >>= 1)
                s += __shfl_xor_sync(0xffffffffu, s, off);
            if (sub == 0) sh_scores[k] = s;
        }
    }
    __syncthreads();

    // ---- softmax (shortened critical path) ----
    // mask indexed by q (faithful to reference broadcast [B,1,Sq,1]).
    const float mval = (1.0f - mask_[b * SEQ + qidx]) * -100000.0f;
    float sc0 = (sh_scores[tid]       + mval) * 0.125f;   // 1/sqrt(64)
    float sc1 = (sh_scores[tid + 128] + mval) * 0.125f;

    // block max: warp tree -> sh_max[warp] -> barrier -> local fold by all
    float m = fmaxf(sc0, sc1);
    #pragma unroll
    for (int off = 16; off >= 1; off >>= 1)
        m = fmaxf(m, __shfl_xor_sync(0xffffffffu, m, off));
    if (lane == 0) sh_max[warp] = m;
    __syncthreads();
    const float rowmax = fmaxf(fmaxf(sh_max[0], sh_max[1]),
                               fmaxf(sh_max[2], sh_max[3]));

    const float e0 = __expf(sc0 - rowmax);
    const float e1 = __expf(sc1 - rowmax);

    // publish e[k] and warp sum partials under ONE barrier
    sh_scores[tid]       = e0;
    sh_scores[tid + 128] = e1;
    float s = e0 + e1;
    #pragma unroll
    for (int off = 16; off >= 1; off >>= 1)
        s += __shfl_xor_sync(0xffffffffu, s, off);
    if (lane == 0) sh_sum[warp] = s;
    __syncthreads();

    const float inv_sum = 1.0f / (sh_sum[0] + sh_sum[1] + sh_sum[2] + sh_sum[3]);

    // attn output straight from registers (coalesced), issued before pass 2
    attn_[(size_t)row * SEQ + tid]       = e0 * inv_sum;
    attn_[(size_t)row * SEQ + tid + 128] = e1 * inv_sum;

    // ---- Pass 2 (unnormalized): acc[d] = sum_k e[k]*(val[k,d]+vs[q,k,d]) ----
    {
        const float* vbase  = v_  + ((size_t)bh  * SEQ) * DIM
                                  + ((size_t)(warp * 64 + half)) * DIM + sub * 4;
        const float* vsbase = vs_ + ((size_t)row * SEQ) * DIM
                                  + ((size_t)(warp * 64 + half)) * DIM + sub * 4;
        float4 acc = make_float4(0.0f, 0.0f, 0.0f, 0.0f);
        #pragma unroll 4
        for (int i = 0; i < 32; ++i) {
            const int k = warp * 64 + i * 2 + half;
            const float a = sh_scores[k];
            float4 vv = *(const float4*)(vbase + (size_t)i * 2 * DIM);
            float4 sv = __ldcs((const float4*)(vsbase + (size_t)i * 2 * DIM));
            acc.x = fmaf(a, vv.x + sv.x, acc.x);
            acc.y = fmaf(a, vv.y + sv.y, acc.y);
            acc.z = fmaf(a, vv.z + sv.z, acc.z);
            acc.w = fmaf(a, vv.w + sv.w, acc.w);
        }
        // fold the two k-halves (lanes sub and sub+16 share d-range)
        acc.x += __shfl_xor_sync(0xffffffffu, acc.x, 16);
        acc.y += __shfl_xor_sync(0xffffffffu, acc.y, 16);
        acc.z += __shfl_xor_sync(0xffffffffu, acc.z, 16);
        acc.w += __shfl_xor_sync(0xffffffffu, acc.w, 16);
        if (half == 0) {
            acc.x *= inv_sum; acc.y *= inv_sum;
            acc.z *= inv_sum; acc.w *= inv_sum;
            *(float4*)(&sh_red[warp][sub * 4]) = acc;
        }
    }
    __syncthreads();

    if (tid < DIM) {
        float r = sh_red[0][tid] + sh_red[1][tid]
                + sh_red[2][tid] + sh_red[3][tid];
        out_[(size_t)row * DIM + tid] = r;
    }
}

extern "C" void kernel_launch(void* const* d_in, const int* in_sizes, int n_in,
                              void* d_out, int out_size) {
    const float* q    = (const float*)d_in[0];
    const float* k    = (const float*)d_in[1];
    const float* v    = (const float*)d_in[2];
    const float* ks   = (const float*)d_in[3];
    const float* vs   = (const float*)d_in[4];
    const float* mask = (const float*)d_in[5];

    float* out  = (float*)d_out;                              // [B,H,S,D]
    float* attn = out + (size_t)BATCH * NHEAD * SEQ * DIM;    // [B,H,S,S]

    const int nrows = BATCH * NHEAD * SEQ;   // 4096
    attn_struct_kernel<<<nrows, 128>>>(q, k, v, ks, vs, mask, out, attn);
}

// round 10
// speedup vs baseline: 1.1079x; 1.0276x over previous
#include <cuda_runtime.h>
#include <cuda_bf16.h>

// Problem constants (B=2, H=8, S=256, D=64)
#define BATCH 2
#define NHEAD 8
#define SEQ   256
#define DIM   64

// Fused structure-attention kernel. 128 threads/block (4 warps), 8 CTAs/SM,
// 64 regs/thread, grid = B*H*S (one CTA per query row).
//
// Key idea this revision: separate cache-hit operands (key/val, L1/L2-hot)
// from the DRAM streams (key_structure/val_structure) so the streaming loops
// issue ONLY miss traffic — 8 front-batched LDG.128 misses per unroll group,
// no cache-hit wavefronts interleaved in the L1tex queue.
//
// Warp lane split: sub = lane&15 owns d-range [4*sub, 4*sub+4),
//                  half = lane>>4 selects one of 2 k-rows per iteration.
// Each warp owns 64 k-rows: k in [warp*64, warp*64+64).
__global__ __launch_bounds__(128, 8) void attn_struct_kernel(
    const float* __restrict__ q_,     // [B,H,S,D]
    const float* __restrict__ k_,     // [B,H,S,D]
    const float* __restrict__ v_,     // [B,H,S,D]
    const float* __restrict__ ks_,    // [B,H,S,S,D]
    const float* __restrict__ vs_,    // [B,H,S,S,D]
    const float* __restrict__ mask_,  // [B,S]
    float* __restrict__ out_,         // [B,H,S,D]
    float* __restrict__ attn_)        // [B,H,S,S]
{
    const int row  = blockIdx.x;         // (b*H + h)*S + q
    const int qidx = row & (SEQ - 1);
    const int bh   = row >> 8;           // b*H + h
    const int b    = bh / NHEAD;

    const int tid  = threadIdx.x;        // 0..127
    const int lane = tid & 31;
    const int warp = tid >> 5;           // 0..3
    const int sub  = lane & 15;          // d/4 slot
    const int half = lane >> 4;          // which of 2 k-rows

    __shared__ float sh_scores[SEQ];     // base scores, then full scores, then e[k]
    __shared__ float sh_red[4][DIM];
    __shared__ float sh_max[4];
    __shared__ float sh_sum[4];
    __shared__ float sh_q[DIM];

    // ---- load q row (64 floats) ----
    if (tid < DIM) sh_q[tid] = q_[(size_t)row * DIM + tid];
    __syncthreads();
    const float4 qv = *(const float4*)(sh_q + sub * 4);

    // ---- Phase B: base scores q.key[k] (L1/L2-hot, compact burst) ----
    // Warp-private k-range; lane sub==0 of (warp,half) writes k = warp*64+2i+half
    // and the SAME thread updates it in phase C — no barrier needed between.
    {
        const float* krow = k_ + ((size_t)bh * SEQ + warp * 64 + half) * DIM + sub * 4;
        #pragma unroll 8
        for (int i = 0; i < 32; ++i) {
            const int k = warp * 64 + i * 2 + half;
            float4 c = *(const float4*)(krow + (size_t)i * 2 * DIM);
            float s = c.x * qv.x + c.y * qv.y + c.z * qv.z + c.w * qv.w;
            #pragma unroll
            for (int off = 8; off >= 1; off >>= 1)
                s += __shfl_xor_sync(0xffffffffu, s, off);
            if (sub == 0) sh_scores[k] = s;
        }
    }

    // ---- Phase C: pure ks DRAM stream, accumulate into base scores ----
    {
        const float* ksrow = ks_ + ((size_t)row * SEQ + warp * 64 + half) * DIM + sub * 4;
        #pragma unroll 8
        for (int i = 0; i < 32; ++i) {
            const int k = warp * 64 + i * 2 + half;
            float4 a = __ldcs((const float4*)(ksrow + (size_t)i * 2 * DIM));
            float s = a.x * qv.x + a.y * qv.y + a.z * qv.z + a.w * qv.w;
            #pragma unroll
            for (int off = 8; off >= 1; off >>= 1)
                s += __shfl_xor_sync(0xffffffffu, s, off);
            if (sub == 0) sh_scores[k] += s;
        }
    }
    __syncthreads();

    // ---- softmax (single-barrier reductions) ----
    // mask indexed by q (faithful to reference broadcast [B,1,Sq,1]).
    const float mval = (1.0f - mask_[b * SEQ + qidx]) * -100000.0f;
    float sc0 = (sh_scores[tid]       + mval) * 0.125f;   // 1/sqrt(64)
    float sc1 = (sh_scores[tid + 128] + mval) * 0.125f;

    float m = fmaxf(sc0, sc1);
    #pragma unroll
    for (int off = 16; off >= 1; off >>= 1)
        m = fmaxf(m, __shfl_xor_sync(0xffffffffu, m, off));
    if (lane == 0) sh_max[warp] = m;
    __syncthreads();
    const float rowmax = fmaxf(fmaxf(sh_max[0], sh_max[1]),
                               fmaxf(sh_max[2], sh_max[3]));

    const float e0 = __expf(sc0 - rowmax);
    const float e1 = __expf(sc1 - rowmax);

    // publish e[k] and warp sum partials under ONE barrier
    sh_scores[tid]       = e0;
    sh_scores[tid + 128] = e1;
    float s = e0 + e1;
    #pragma unroll
    for (int off = 16; off >= 1; off >>= 1)
        s += __shfl_xor_sync(0xffffffffu, s, off);
    if (lane == 0) sh_sum[warp] = s;
    __syncthreads();

    const float inv_sum = 1.0f / (sh_sum[0] + sh_sum[1] + sh_sum[2] + sh_sum[3]);

    // attn output straight from registers (coalesced)
    attn_[(size_t)row * SEQ + tid]       = e0 * inv_sum;
    attn_[(size_t)row * SEQ + tid + 128] = e1 * inv_sum;

    // ---- Pass 2 ----
    float4 acc = make_float4(0.0f, 0.0f, 0.0f, 0.0f);

    // Phase E: acc = sum_k e[k]*val[k,d]   (val L1/L2-hot, compact burst)
    {
        const float* vbase = v_ + ((size_t)bh * SEQ + warp * 64 + half) * DIM + sub * 4;
        #pragma unroll 8
        for (int i = 0; i < 32; ++i) {
            const int k = warp * 64 + i * 2 + half;
            const float a = sh_scores[k];
            float4 vv = *(const float4*)(vbase + (size_t)i * 2 * DIM);
            acc.x = fmaf(a, vv.x, acc.x);
            acc.y = fmaf(a, vv.y, acc.y);
            acc.z = fmaf(a, vv.z, acc.z);
            acc.w = fmaf(a, vv.w, acc.w);
        }
    }

    // Phase F: pure vs DRAM stream, accumulate
    {
        const float* vsbase = vs_ + ((size_t)row * SEQ + warp * 64 + half) * DIM + sub * 4;
        #pragma unroll 8
        for (int i = 0; i < 32; ++i) {
            const int k = warp * 64 + i * 2 + half;
            const float a = sh_scores[k];
            float4 sv = __ldcs((const float4*)(vsbase + (size_t)i * 2 * DIM));
            acc.x = fmaf(a, sv.x, acc.x);
            acc.y = fmaf(a, sv.y, acc.y);
            acc.z = fmaf(a, sv.z, acc.z);
            acc.w = fmaf(a, sv.w, acc.w);
        }
    }

    // fold the two k-halves (lanes sub and sub+16 share d-range)
    acc.x += __shfl_xor_sync(0xffffffffu, acc.x, 16);
    acc.y += __shfl_xor_sync(0xffffffffu, acc.y, 16);
    acc.z += __shfl_xor_sync(0xffffffffu, acc.z, 16);
    acc.w += __shfl_xor_sync(0xffffffffu, acc.w, 16);
    if (half == 0) {
        acc.x *= inv_sum; acc.y *= inv_sum;
        acc.z *= inv_sum; acc.w *= inv_sum;
        *(float4*)(&sh_red[warp][sub * 4]) = acc;
    }
    __syncthreads();

    if (tid < DIM) {
        float r = sh_red[0][tid] + sh_red[1][tid]
                + sh_red[2][tid] + sh_red[3][tid];
        out_[(size_t)row * DIM + tid] = r;
    }
}

extern "C" void kernel_launch(void* const* d_in, const int* in_sizes, int n_in,
                              void* d_out, int out_size) {
    const float* q    = (const float*)d_in[0];
    const float* k    = (const float*)d_in[1];
    const float* v    = (const float*)d_in[2];
    const float* ks   = (const float*)d_in[3];
    const float* vs   = (const float*)d_in[4];
    const float* mask = (const float*)d_in[5];

    float* out  = (float*)d_out;                              // [B,H,S,D]
    float* attn = out + (size_t)BATCH * NHEAD * SEQ * DIM;    // [B,H,S,S]

    const int nrows = BATCH * NHEAD * SEQ;   // 4096
    attn_struct_kernel<<<nrows, 128>>>(q, k, v, ks, vs, mask, out, attn);
}